// round 10
// baseline (speedup 1.0000x reference)
#include <cuda_runtime.h>
#include <cuda_bf16.h>
#include <stdint.h>
#include <math.h>

#define BSZ   32
#define NPAT  576
#define WCON  32
#define DDIM  256
#define MROWS (BSZ*NPAT)   // 18432 patches
#define NCON  (BSZ*WCON)   // 1024 concepts

#define CT 128             // concepts per CTA tile (M)
#define PT 128             // patches per tile (N)
#define NT_N (MROWS/PT)    // 144 patch tiles
#define NT_C (NCON/CT)     // 8 concept tiles
#define PPG  4             // patch tiles per CTA
#define NPG  (NT_N/PPG)    // 36 -> grid 36 x 8 = 288 CTAs (2/SM, single wave)
#define NCHUNK (4*PPG)     // 16 steps per CTA
#define NCTAS (NPG*NT_C)   // 288

// scratch (device globals; no allocation allowed)
__device__ __nv_bfloat16 g_conb[NCON * DDIM];
__device__ __nv_bfloat16 g_imgb[MROWS * DDIM];
__device__ unsigned      g_enc[NCON * BSZ];   // running max[concept j][image m], encoded
__device__ unsigned      g_done;              // completion ticket counter

// ---------------- helpers ----------------
static __device__ __forceinline__ uint32_t smem_u32(const void* p) {
    uint32_t a;
    asm("{ .reg .u64 t; cvta.to.shared.u64 t, %1; cvt.u32.u64 %0, t; }" : "=r"(a) : "l"(p));
    return a;
}
static __device__ __forceinline__ unsigned enc_f(float f) {
    unsigned b = __float_as_uint(f);
    return (b & 0x80000000u) ? ~b : (b | 0x80000000u);
}
static __device__ __forceinline__ float dec_f(unsigned u) {
    unsigned b = (u & 0x80000000u) ? (u & 0x7FFFFFFFu) : ~u;
    return __uint_as_float(b);
}
static __device__ __forceinline__ void cpasync16(uint32_t dst, const void* src) {
    asm volatile("cp.async.cg.shared.global [%0], [%1], 16;" :: "r"(dst), "l"(src));
}
static __device__ __forceinline__ void ldsm_x4(uint32_t* r, uint32_t addr) {
    asm volatile("ldmatrix.sync.aligned.m8n8.x4.shared.b16 {%0,%1,%2,%3}, [%4];"
                 : "=r"(r[0]), "=r"(r[1]), "=r"(r[2]), "=r"(r[3]) : "r"(addr));
}
static __device__ __forceinline__ void mma_bf16(float* c, const uint32_t* a, const uint32_t* b) {
    asm volatile("mma.sync.aligned.m16n8k16.row.col.f32.bf16.bf16.f32 "
                 "{%0,%1,%2,%3}, {%4,%5,%6,%7}, {%8,%9}, {%0,%1,%2,%3};"
                 : "+f"(c[0]), "+f"(c[1]), "+f"(c[2]), "+f"(c[3])
                 : "r"(a[0]), "r"(a[1]), "r"(a[2]), "r"(a[3]), "r"(b[0]), "r"(b[1]));
}
static __device__ __forceinline__ uint32_t bf2_pack(float x, float y) {
    __nv_bfloat162 t = __floats2bfloat162_rn(x, y);
    return *reinterpret_cast<uint32_t*>(&t);
}

// ---------------------------------------------------------------------------
// Prep: L2-normalize img+con rows (fp32 -> bf16), 2 rows per warp for ILP,
// contiguous 16B stores; also zero g_enc and g_done.
// ---------------------------------------------------------------------------
__global__ void __launch_bounds__(512) prep_kernel(const float* __restrict__ img,
                                                   const float* __restrict__ con) {
    const int tid = threadIdx.x;
    if (blockIdx.x < 64) {
        g_enc[blockIdx.x * 512 + tid] = 0u;
        if (blockIdx.x == 0 && tid == 0) g_done = 0u;
    }

    int gw = blockIdx.x * 16 + (tid >> 5);        // warp id -> row pair
    int lane = tid & 31;
    int r0 = gw * 2;
    if (r0 >= MROWS + NCON) return;

    const float* src0; __nv_bfloat16* dst0; int row0;
    const float* src1; __nv_bfloat16* dst1; int row1;
    if (r0 < MROWS) { src0 = img; dst0 = g_imgb; row0 = r0; }
    else            { src0 = con; dst0 = g_conb; row0 = r0 - MROWS; }
    int r1 = r0 + 1;
    if (r1 < MROWS) { src1 = img; dst1 = g_imgb; row1 = r1; }
    else            { src1 = con; dst1 = g_conb; row1 = r1 - MROWS; }

    // lane covers 8 contiguous floats per row
    const float4* p0 = reinterpret_cast<const float4*>(src0 + (size_t)row0 * DDIM) + lane * 2;
    const float4* p1 = reinterpret_cast<const float4*>(src1 + (size_t)row1 * DDIM) + lane * 2;
    float4 a0 = p0[0], a1 = p0[1];
    float4 b0 = p1[0], b1 = p1[1];

    float sa = a0.x*a0.x + a0.y*a0.y + a0.z*a0.z + a0.w*a0.w
             + a1.x*a1.x + a1.y*a1.y + a1.z*a1.z + a1.w*a1.w;
    float sb = b0.x*b0.x + b0.y*b0.y + b0.z*b0.z + b0.w*b0.w
             + b1.x*b1.x + b1.y*b1.y + b1.z*b1.z + b1.w*b1.w;
#pragma unroll
    for (int o = 16; o > 0; o >>= 1) {
        sa += __shfl_xor_sync(0xffffffffu, sa, o);
        sb += __shfl_xor_sync(0xffffffffu, sb, o);
    }
    float ra = 1.0f / fmaxf(sqrtf(sa), 1e-12f);
    float rb = 1.0f / fmaxf(sqrtf(sb), 1e-12f);

    uint4 oa, ob;
    oa.x = bf2_pack(a0.x*ra, a0.y*ra);
    oa.y = bf2_pack(a0.z*ra, a0.w*ra);
    oa.z = bf2_pack(a1.x*ra, a1.y*ra);
    oa.w = bf2_pack(a1.z*ra, a1.w*ra);
    ob.x = bf2_pack(b0.x*rb, b0.y*rb);
    ob.y = bf2_pack(b0.z*rb, b0.w*rb);
    ob.z = bf2_pack(b1.x*rb, b1.y*rb);
    ob.w = bf2_pack(b1.z*rb, b1.w*rb);

    reinterpret_cast<uint4*>(dst0 + (size_t)row0 * DDIM)[lane] = oa;
    reinterpret_cast<uint4*>(dst1 + (size_t)row1 * DDIM)[lane] = ob;
}

// ---------------------------------------------------------------------------
// Fused GEMM + max-over-patches + (last CTA) loss.
// CTA tile 128x128, K=256. A resident 64KB (4 kc chunks of 128x128B).
// B: 3-deep ring of 16KB chunks. smem = 112KB -> 2 CTAs/SM.
// 256 threads = 8 warps (4m x 2n), warp tile 32x64.
// ---------------------------------------------------------------------------
#define SMA_CHUNK (CT * 128)                // 16KB per A k-chunk
#define SMA_BYTES (4 * SMA_CHUNK)           // 64KB
#define SMB_CHUNK (PT * 128)                // 16KB per B chunk
#define SMEM_DYN  (SMA_BYTES + 3 * SMB_CHUNK)   // 112KB

static __device__ __forceinline__ void stage_B(int ptile, int kc, uint32_t buf, int tid) {
    const __nv_bfloat16* bsrc = g_imgb + (size_t)ptile * PT * DDIM + kc * 64;
#pragma unroll
    for (int i = tid; i < 1024; i += 256) {
        int r = i >> 3, s = i & 7;
        cpasync16(buf + r * 128 + ((s ^ (r & 7)) << 4), bsrc + (size_t)r * DDIM + s * 8);
    }
}

static __device__ __forceinline__ void compute_chunk(float acc[2][8][4],
                                                     uint32_t bufA, uint32_t bufB,
                                                     int warp_m, int warp_n, int lane) {
#pragma unroll
    for (int ks = 0; ks < 4; ks++) {
        uint32_t a[2][4];
#pragma unroll
        for (int mi = 0; mi < 2; mi++) {
            int row = warp_m * 32 + mi * 16 + (lane & 15);
            uint32_t g = ((ks << 1) + (lane >> 4)) ^ (row & 7);
            ldsm_x4(a[mi], bufA + row * 128 + (g << 4));
        }
        uint32_t b[4][4];
#pragma unroll
        for (int pi = 0; pi < 4; pi++) {
            int nloc = warp_n * 64 + pi * 16 + ((lane >> 4) << 3) + (lane & 7);
            uint32_t g = ((ks << 1) + ((lane >> 3) & 1)) ^ (nloc & 7);
            ldsm_x4(b[pi], bufB + nloc * 128 + (g << 4));
        }
#pragma unroll
        for (int mi = 0; mi < 2; mi++)
#pragma unroll
            for (int pi = 0; pi < 4; pi++) {
                mma_bf16(acc[mi][2 * pi + 0], a[mi], &b[pi][0]);
                mma_bf16(acc[mi][2 * pi + 1], a[mi], &b[pi][2]);
            }
    }
}

__global__ void __launch_bounds__(256, 2) sim_mma_kernel(const int* __restrict__ lens,
                                                         const float* __restrict__ scale_p,
                                                         const float* __restrict__ bias_p,
                                                         float* __restrict__ out) {
    extern __shared__ char sm[];
    const int pgrp  = blockIdx.x;
    const int ctile = blockIdx.y;
    const int tid = threadIdx.x;
    const int wid = tid >> 5;
    const int lane = tid & 31;
    const int warp_m = wid & 3;        // 4 warps in m (32 rows each)
    const int warp_n = wid >> 2;       // 2 warps in n (64 cols each)
    const int pt0 = pgrp * PPG;

    uint32_t A = smem_u32(sm);
    uint32_t B[3];
#pragma unroll
    for (int i = 0; i < 3; i++) B[i] = A + SMA_BYTES + i * SMB_CHUNK;

    // Stage resident A (64KB) + prime 3 B chunks.
    {
        const __nv_bfloat16* asrc = g_conb + (size_t)ctile * CT * DDIM;
#pragma unroll
        for (int i = tid; i < 4096; i += 256) {
            int r = i >> 5, u = i & 31;
            int kc = u >> 3, s = u & 7;
            cpasync16(A + kc * SMA_CHUNK + r * 128 + ((s ^ (r & 7)) << 4),
                      asrc + (size_t)r * DDIM + kc * 64 + s * 8);
        }
    }
    stage_B(pt0, 0, B[0], tid);
    asm volatile("cp.async.commit_group;" ::: "memory");   // g0: A + B0
    stage_B(pt0, 1, B[1], tid);
    asm volatile("cp.async.commit_group;" ::: "memory");   // g1
    stage_B(pt0, 2, B[2], tid);
    asm volatile("cp.async.commit_group;" ::: "memory");   // g2

    float acc[2][8][4];
    int bi = 0;                          // t % 3
    for (int t = 0; t < NCHUNK; t++) {
        int kc = t & 3;
        if (kc == 0) {
#pragma unroll
            for (int mi = 0; mi < 2; mi++)
#pragma unroll
                for (int ni = 0; ni < 8; ni++)
#pragma unroll
                    for (int c = 0; c < 4; c++) acc[mi][ni][c] = 0.f;
        }

        asm volatile("cp.async.wait_group 2;" ::: "memory");   // chunk t resident
        __syncthreads();

        compute_chunk(acc, A + kc * SMA_CHUNK, B[bi], warp_m, warp_n, lane);

        __syncthreads();                                       // retire B[bi] reads
        int tn = t + 3;
        if (tn < NCHUNK) stage_B(pt0 + (tn >> 2), tn & 3, B[bi], tid);
        asm volatile("cp.async.commit_group;" ::: "memory");
        bi = (bi == 2) ? 0 : bi + 1;

        if (kc == 3) {
            // Epilogue (registers + atomics only; overlaps in-flight staging).
            const int ptile = pt0 + (t >> 2);
            const int p0 = ptile * PT;
            const int m0 = p0 / NPAT;
            const int b  = (m0 + 1) * NPAT - p0;   // image boundary within tile
#pragma unroll
            for (int mi = 0; mi < 2; mi++) {
                float mx00 = -1e30f, mx01 = -1e30f;
                float mx10 = -1e30f, mx11 = -1e30f;
#pragma unroll
                for (int ni = 0; ni < 8; ni++) {
                    int lc = warp_n * 64 + ni * 8 + (lane & 3) * 2;
                    if (lc < b) {
                        mx00 = fmaxf(mx00, fmaxf(acc[mi][ni][0], acc[mi][ni][1]));
                        mx10 = fmaxf(mx10, fmaxf(acc[mi][ni][2], acc[mi][ni][3]));
                    } else {
                        mx01 = fmaxf(mx01, fmaxf(acc[mi][ni][0], acc[mi][ni][1]));
                        mx11 = fmaxf(mx11, fmaxf(acc[mi][ni][2], acc[mi][ni][3]));
                    }
                }
#pragma unroll
                for (int o = 1; o <= 2; o <<= 1) {
                    mx00 = fmaxf(mx00, __shfl_xor_sync(0xffffffffu, mx00, o));
                    mx01 = fmaxf(mx01, __shfl_xor_sync(0xffffffffu, mx01, o));
                    mx10 = fmaxf(mx10, __shfl_xor_sync(0xffffffffu, mx10, o));
                    mx11 = fmaxf(mx11, __shfl_xor_sync(0xffffffffu, mx11, o));
                }
                if ((lane & 3) == 0) {
                    int r0 = ctile * CT + warp_m * 32 + mi * 16 + (lane >> 2);
                    atomicMax(&g_enc[r0 * BSZ + m0],       enc_f(mx00));
                    atomicMax(&g_enc[(r0 + 8) * BSZ + m0], enc_f(mx10));
                    if (b < PT) {
                        atomicMax(&g_enc[r0 * BSZ + m0 + 1],       enc_f(mx01));
                        atomicMax(&g_enc[(r0 + 8) * BSZ + m0 + 1], enc_f(mx11));
                    }
                }
            }
        }
    }

    // ---- last-CTA loss epilogue ----
    __threadfence();
    __syncthreads();
    __shared__ int s_last;
    if (tid == 0) s_last = (atomicAdd(&g_done, 1u) == NCTAS - 1) ? 1 : 0;
    __syncthreads();
    if (!s_last) return;

    // 1024 (m,c) pairs, 4 per thread; g_enc via L2 (atomics wrote L2).
    float t_ = expf(fminf(fmaxf(scale_p[0], -10.f), 10.f));
    float bia = bias_p[0];
    float part = 0.f;
#pragma unroll
    for (int q = 0; q < 4; q++) {
        int p = tid * 4 + q;
        int m = p >> 5, c = p & 31;
        int L = lens[c];
        float s = 0.f;
        for (int w = 0; w < L; w++)
            s += dec_f(__ldcg(&g_enc[((c << 5) + w) * BSZ + m]));
        float sim = s / (float)L;
        float logit = fminf(fmaxf(t_ * sim + bia, -50.f), 50.f);
        float zx = ((m == c) ? 1.f : -1.f) * logit;
        part += -(fminf(zx, 0.f) - log1pf(expf(-fabsf(zx))));
    }
#pragma unroll
    for (int o = 16; o > 0; o >>= 1) part += __shfl_xor_sync(0xffffffffu, part, o);
    __shared__ float red[8];
    if (lane == 0) red[wid] = part;
    __syncthreads();
    if (tid == 0) {
        float tot = 0.f;
#pragma unroll
        for (int i = 0; i < 8; i++) tot += red[i];
        out[0] = tot * (1.0f / (BSZ * BSZ));
    }
}

extern "C" void kernel_launch(void* const* d_in, const int* in_sizes, int n_in,
                              void* d_out, int out_size) {
    const float* img = nullptr; const float* con = nullptr;
    const int* lens = nullptr; const float* sc = nullptr; const float* bi = nullptr;
    for (int i = 0; i < n_in; i++) {
        int s = in_sizes[i];
        if (s == MROWS * DDIM)      img = (const float*)d_in[i];
        else if (s == NCON * DDIM)  con = (const float*)d_in[i];
        else if (s == BSZ)          lens = (const int*)d_in[i];
        else if (s == 1) { if (!sc) sc = (const float*)d_in[i]; else bi = (const float*)d_in[i]; }
    }

    cudaFuncSetAttribute(sim_mma_kernel, cudaFuncAttributeMaxDynamicSharedMemorySize, SMEM_DYN);

    int rows2 = (MROWS + NCON) / 2;                 // 9728 row-pairs (warps)
    prep_kernel<<<(rows2 + 15) / 16, 512>>>(img, con);

    dim3 grid(NPG, NT_C);
    sim_mma_kernel<<<grid, 256, SMEM_DYN>>>(lens, sc, bi, (float*)d_out);
}

// round 11
// speedup vs baseline: 1.1725x; 1.1725x over previous
#include <cuda_runtime.h>
#include <cuda_bf16.h>
#include <stdint.h>
#include <math.h>

#define BSZ   32
#define NPAT  576
#define WCON  32
#define DDIM  256
#define MROWS (BSZ*NPAT)   // 18432 patches
#define NCON  (BSZ*WCON)   // 1024 concepts

#define CT 128             // concepts per CTA tile (M)
#define PT 128             // patches per half-tile (N)
#define NT_N (MROWS/PT)    // 144 patch tiles
#define NT_C (NCON/CT)     // 8 concept tiles
#define PPC  8             // patch tiles per CTA (4 per half)
#define NPG  (NT_N/PPC)    // 18 -> grid 18 x 8 = 144 CTAs (1/SM, 1 wave)
#define NCHUNK 16          // chunks per half (4 ptiles x 4 k-slices)
#define NCTAS (NPG*NT_C)   // 144

// scratch (device globals; no allocation allowed)
__device__ __nv_bfloat16 g_conb[NCON * DDIM];
__device__ __nv_bfloat16 g_imgb[MROWS * DDIM];
__device__ unsigned      g_enc[NCON * BSZ];   // running max[concept j][image m], encoded
__device__ unsigned      g_done;              // completion ticket counter

// ---------------- helpers ----------------
static __device__ __forceinline__ uint32_t smem_u32(const void* p) {
    uint32_t a;
    asm("{ .reg .u64 t; cvta.to.shared.u64 t, %1; cvt.u32.u64 %0, t; }" : "=r"(a) : "l"(p));
    return a;
}
static __device__ __forceinline__ unsigned enc_f(float f) {
    unsigned b = __float_as_uint(f);
    return (b & 0x80000000u) ? ~b : (b | 0x80000000u);
}
static __device__ __forceinline__ float dec_f(unsigned u) {
    unsigned b = (u & 0x80000000u) ? (u & 0x7FFFFFFFu) : ~u;
    return __uint_as_float(b);
}
static __device__ __forceinline__ void cpasync16(uint32_t dst, const void* src) {
    asm volatile("cp.async.cg.shared.global [%0], [%1], 16;" :: "r"(dst), "l"(src));
}
static __device__ __forceinline__ void ldsm_x4(uint32_t* r, uint32_t addr) {
    asm volatile("ldmatrix.sync.aligned.m8n8.x4.shared.b16 {%0,%1,%2,%3}, [%4];"
                 : "=r"(r[0]), "=r"(r[1]), "=r"(r[2]), "=r"(r[3]) : "r"(addr));
}
static __device__ __forceinline__ void mma_bf16(float* c, const uint32_t* a, const uint32_t* b) {
    asm volatile("mma.sync.aligned.m16n8k16.row.col.f32.bf16.bf16.f32 "
                 "{%0,%1,%2,%3}, {%4,%5,%6,%7}, {%8,%9}, {%0,%1,%2,%3};"
                 : "+f"(c[0]), "+f"(c[1]), "+f"(c[2]), "+f"(c[3])
                 : "r"(a[0]), "r"(a[1]), "r"(a[2]), "r"(a[3]), "r"(b[0]), "r"(b[1]));
}
static __device__ __forceinline__ uint32_t bf2_pack(float x, float y) {
    __nv_bfloat162 t = __floats2bfloat162_rn(x, y);
    return *reinterpret_cast<uint32_t*>(&t);
}
static __device__ __forceinline__ void barh(int id) {
    asm volatile("bar.sync %0, 256;" :: "r"(id) : "memory");
}

// ---------------------------------------------------------------------------
// Prep: L2-normalize img+con rows (fp32 -> bf16), 2 rows per warp for ILP,
// contiguous 16B stores; also zero g_enc and g_done.
// ---------------------------------------------------------------------------
__global__ void __launch_bounds__(512) prep_kernel(const float* __restrict__ img,
                                                   const float* __restrict__ con) {
    const int tid = threadIdx.x;
    if (blockIdx.x < 64) {
        g_enc[blockIdx.x * 512 + tid] = 0u;
        if (blockIdx.x == 0 && tid == 0) g_done = 0u;
    }

    int gw = blockIdx.x * 16 + (tid >> 5);
    int lane = tid & 31;
    int r0 = gw * 2;
    if (r0 >= MROWS + NCON) return;

    const float* src0; __nv_bfloat16* dst0; int row0;
    const float* src1; __nv_bfloat16* dst1; int row1;
    if (r0 < MROWS) { src0 = img; dst0 = g_imgb; row0 = r0; }
    else            { src0 = con; dst0 = g_conb; row0 = r0 - MROWS; }
    int r1 = r0 + 1;
    if (r1 < MROWS) { src1 = img; dst1 = g_imgb; row1 = r1; }
    else            { src1 = con; dst1 = g_conb; row1 = r1 - MROWS; }

    const float4* p0 = reinterpret_cast<const float4*>(src0 + (size_t)row0 * DDIM) + lane * 2;
    const float4* p1 = reinterpret_cast<const float4*>(src1 + (size_t)row1 * DDIM) + lane * 2;
    float4 a0 = p0[0], a1 = p0[1];
    float4 b0 = p1[0], b1 = p1[1];

    float sa = a0.x*a0.x + a0.y*a0.y + a0.z*a0.z + a0.w*a0.w
             + a1.x*a1.x + a1.y*a1.y + a1.z*a1.z + a1.w*a1.w;
    float sb = b0.x*b0.x + b0.y*b0.y + b0.z*b0.z + b0.w*b0.w
             + b1.x*b1.x + b1.y*b1.y + b1.z*b1.z + b1.w*b1.w;
#pragma unroll
    for (int o = 16; o > 0; o >>= 1) {
        sa += __shfl_xor_sync(0xffffffffu, sa, o);
        sb += __shfl_xor_sync(0xffffffffu, sb, o);
    }
    float ra = 1.0f / fmaxf(sqrtf(sa), 1e-12f);
    float rb = 1.0f / fmaxf(sqrtf(sb), 1e-12f);

    uint4 oa, ob;
    oa.x = bf2_pack(a0.x*ra, a0.y*ra);
    oa.y = bf2_pack(a0.z*ra, a0.w*ra);
    oa.z = bf2_pack(a1.x*ra, a1.y*ra);
    oa.w = bf2_pack(a1.z*ra, a1.w*ra);
    ob.x = bf2_pack(b0.x*rb, b0.y*rb);
    ob.y = bf2_pack(b0.z*rb, b0.w*rb);
    ob.z = bf2_pack(b1.x*rb, b1.y*rb);
    ob.w = bf2_pack(b1.z*rb, b1.w*rb);

    reinterpret_cast<uint4*>(dst0 + (size_t)row0 * DDIM)[lane] = oa;
    reinterpret_cast<uint4*>(dst1 + (size_t)row1 * DDIM)[lane] = ob;
}

// ---------------------------------------------------------------------------
// Fused GEMM + max-over-patches + (last CTA) loss.
// 512 threads = two independent 256-thread pipelines (named barriers only).
// A (128 x K=256) resident 64KB, shared read-only by both halves.
// Each half: private 4-deep B ring (4 x 16KB), alternating 128-patch tiles.
// smem = 192KB, 1 CTA/SM, grid 18 x 8 = 144 (single wave).
// ---------------------------------------------------------------------------
#define SMA_CHUNK (CT * 128)                // 16KB per A k-chunk
#define SMA_BYTES (4 * SMA_CHUNK)           // 64KB
#define SMB_CHUNK (PT * 128)                // 16KB per B chunk
#define SMEM_DYN  (SMA_BYTES + 2 * 4 * SMB_CHUNK)   // 192KB

static __device__ __forceinline__ void stage_B(int ptile, int kc, uint32_t buf, int tid_h) {
    const __nv_bfloat16* bsrc = g_imgb + (size_t)ptile * PT * DDIM + kc * 64;
#pragma unroll
    for (int i = tid_h; i < 1024; i += 256) {
        int r = i >> 3, s = i & 7;
        cpasync16(buf + r * 128 + ((s ^ (r & 7)) << 4), bsrc + (size_t)r * DDIM + s * 8);
    }
}

static __device__ __forceinline__ void compute_chunk(float acc[2][8][4],
                                                     uint32_t bufA, uint32_t bufB,
                                                     int warp_m, int warp_n, int lane) {
#pragma unroll
    for (int ks = 0; ks < 4; ks++) {
        uint32_t a[2][4];
#pragma unroll
        for (int mi = 0; mi < 2; mi++) {
            int row = warp_m * 32 + mi * 16 + (lane & 15);
            uint32_t g = ((ks << 1) + (lane >> 4)) ^ (row & 7);
            ldsm_x4(a[mi], bufA + row * 128 + (g << 4));
        }
        uint32_t b[4][4];
#pragma unroll
        for (int pi = 0; pi < 4; pi++) {
            int nloc = warp_n * 64 + pi * 16 + ((lane >> 4) << 3) + (lane & 7);
            uint32_t g = ((ks << 1) + ((lane >> 3) & 1)) ^ (nloc & 7);
            ldsm_x4(b[pi], bufB + nloc * 128 + (g << 4));
        }
#pragma unroll
        for (int mi = 0; mi < 2; mi++)
#pragma unroll
            for (int pi = 0; pi < 4; pi++) {
                mma_bf16(acc[mi][2 * pi + 0], a[mi], &b[pi][0]);
                mma_bf16(acc[mi][2 * pi + 1], a[mi], &b[pi][2]);
            }
    }
}

__global__ void __launch_bounds__(512, 1) sim_mma_kernel(const int* __restrict__ lens,
                                                         const float* __restrict__ scale_p,
                                                         const float* __restrict__ bias_p,
                                                         float* __restrict__ out) {
    extern __shared__ char sm[];
    const int pgrp  = blockIdx.x;
    const int ctile = blockIdx.y;
    const int tid = threadIdx.x;
    const int half = tid >> 8;             // 0 or 1
    const int tid_h = tid & 255;
    const int hw = tid_h >> 5;             // warp within half (0..7)
    const int lane = tid & 31;
    const int warp_m = hw & 3;             // 4 warps in m (32 rows each)
    const int warp_n = hw >> 2;            // 2 warps in n (64 cols each)

    uint32_t A = smem_u32(sm);
    uint32_t B[4];
#pragma unroll
    for (int i = 0; i < 4; i++)
        B[i] = A + SMA_BYTES + (half * 4 + i) * SMB_CHUNK;

    // ptile for chunk t of this half: pgrp*8 + (t>>2)*2 + half, k-slice t&3
    const int ptbase = pgrp * PPC + half;

    // Stage A (all 512 threads) -> commit c0
    {
        const __nv_bfloat16* asrc = g_conb + (size_t)ctile * CT * DDIM;
#pragma unroll
        for (int i = tid; i < 4096; i += 512) {
            int r = i >> 5, u = i & 31;
            int kc = u >> 3, s = u & 7;
            cpasync16(A + kc * SMA_CHUNK + r * 128 + ((s ^ (r & 7)) << 4),
                      asrc + (size_t)r * DDIM + kc * 64 + s * 8);
        }
        asm volatile("cp.async.commit_group;" ::: "memory");
    }
    // Prime B chunks 0..2 for this half -> commits c1..c3
    stage_B(ptbase + 0, 0, B[0], tid_h);
    asm volatile("cp.async.commit_group;" ::: "memory");
    stage_B(ptbase + 0, 1, B[1], tid_h);
    asm volatile("cp.async.commit_group;" ::: "memory");
    stage_B(ptbase + 0, 2, B[2], tid_h);
    asm volatile("cp.async.commit_group;" ::: "memory");

    // A must be fully resident (written by BOTH halves) before any compute.
    asm volatile("cp.async.wait_group 3;" ::: "memory");
    __syncthreads();       // the only full-CTA barrier in the mainloop

    const int barid = half + 1;
    float acc[2][8][4];
    for (int t = 0; t < NCHUNK; t++) {
        int kc = t & 3;
        if (kc == 0) {
#pragma unroll
            for (int mi = 0; mi < 2; mi++)
#pragma unroll
                for (int ni = 0; ni < 8; ni++)
#pragma unroll
                    for (int c = 0; c < 4; c++) acc[mi][ni][c] = 0.f;
        }

        asm volatile("cp.async.wait_group 2;" ::: "memory");   // chunk t resident
        barh(barid);   // half-barrier: all 8 warps ready; retires compute t-1

        int tn = t + 3;
        if (tn < NCHUNK) stage_B(ptbase + (tn >> 2) * 2, tn & 3, B[tn & 3], tid_h);
        asm volatile("cp.async.commit_group;" ::: "memory");

        compute_chunk(acc, A + kc * SMA_CHUNK, B[t & 3], warp_m, warp_n, lane);

        if (kc == 3) {
            // Epilogue (registers + atomics only; overlaps in-flight staging).
            const int ptile = ptbase + (t >> 2) * 2;
            const int p0 = ptile * PT;
            const int m0 = p0 / NPAT;
            const int b  = (m0 + 1) * NPAT - p0;   // image boundary within tile
#pragma unroll
            for (int mi = 0; mi < 2; mi++) {
                float mx00 = -1e30f, mx01 = -1e30f;
                float mx10 = -1e30f, mx11 = -1e30f;
#pragma unroll
                for (int ni = 0; ni < 8; ni++) {
                    int lc = warp_n * 64 + ni * 8 + (lane & 3) * 2;
                    if (lc < b) {
                        mx00 = fmaxf(mx00, fmaxf(acc[mi][ni][0], acc[mi][ni][1]));
                        mx10 = fmaxf(mx10, fmaxf(acc[mi][ni][2], acc[mi][ni][3]));
                    } else {
                        mx01 = fmaxf(mx01, fmaxf(acc[mi][ni][0], acc[mi][ni][1]));
                        mx11 = fmaxf(mx11, fmaxf(acc[mi][ni][2], acc[mi][ni][3]));
                    }
                }
#pragma unroll
                for (int o = 1; o <= 2; o <<= 1) {
                    mx00 = fmaxf(mx00, __shfl_xor_sync(0xffffffffu, mx00, o));
                    mx01 = fmaxf(mx01, __shfl_xor_sync(0xffffffffu, mx01, o));
                    mx10 = fmaxf(mx10, __shfl_xor_sync(0xffffffffu, mx10, o));
                    mx11 = fmaxf(mx11, __shfl_xor_sync(0xffffffffu, mx11, o));
                }
                if ((lane & 3) == 0) {
                    int r0 = ctile * CT + warp_m * 32 + mi * 16 + (lane >> 2);
                    atomicMax(&g_enc[r0 * BSZ + m0],       enc_f(mx00));
                    atomicMax(&g_enc[(r0 + 8) * BSZ + m0], enc_f(mx10));
                    if (b < PT) {
                        atomicMax(&g_enc[r0 * BSZ + m0 + 1],       enc_f(mx01));
                        atomicMax(&g_enc[(r0 + 8) * BSZ + m0 + 1], enc_f(mx11));
                    }
                }
            }
        }
    }

    // ---- last-CTA loss epilogue ----
    __threadfence();
    __syncthreads();
    __shared__ int s_last;
    if (tid == 0) s_last = (atomicAdd(&g_done, 1u) == NCTAS - 1) ? 1 : 0;
    __syncthreads();
    if (!s_last) return;

    float t_ = expf(fminf(fmaxf(scale_p[0], -10.f), 10.f));
    float bia = bias_p[0];
    float part = 0.f;
#pragma unroll
    for (int q = 0; q < 2; q++) {
        int p = tid * 2 + q;
        int m = p >> 5, c = p & 31;
        int L = lens[c];
        float s = 0.f;
        for (int w = 0; w < L; w++)
            s += dec_f(__ldcg(&g_enc[((c << 5) + w) * BSZ + m]));
        float sim = s / (float)L;
        float logit = fminf(fmaxf(t_ * sim + bia, -50.f), 50.f);
        float zx = ((m == c) ? 1.f : -1.f) * logit;
        part += -(fminf(zx, 0.f) - log1pf(expf(-fabsf(zx))));
    }
#pragma unroll
    for (int o = 16; o > 0; o >>= 1) part += __shfl_xor_sync(0xffffffffu, part, o);
    __shared__ float red[16];
    if (lane == 0) red[tid >> 5] = part;
    __syncthreads();
    if (tid == 0) {
        float tot = 0.f;
#pragma unroll
        for (int i = 0; i < 16; i++) tot += red[i];
        out[0] = tot * (1.0f / (BSZ * BSZ));
    }
}

extern "C" void kernel_launch(void* const* d_in, const int* in_sizes, int n_in,
                              void* d_out, int out_size) {
    const float* img = nullptr; const float* con = nullptr;
    const int* lens = nullptr; const float* sc = nullptr; const float* bi = nullptr;
    for (int i = 0; i < n_in; i++) {
        int s = in_sizes[i];
        if (s == MROWS * DDIM)      img = (const float*)d_in[i];
        else if (s == NCON * DDIM)  con = (const float*)d_in[i];
        else if (s == BSZ)          lens = (const int*)d_in[i];
        else if (s == 1) { if (!sc) sc = (const float*)d_in[i]; else bi = (const float*)d_in[i]; }
    }

    cudaFuncSetAttribute(sim_mma_kernel, cudaFuncAttributeMaxDynamicSharedMemorySize, SMEM_DYN);

    int rows2 = (MROWS + NCON) / 2;
    prep_kernel<<<(rows2 + 15) / 16, 512>>>(img, con);

    dim3 grid(NPG, NT_C);
    sim_mma_kernel<<<grid, 512, SMEM_DYN>>>(lens, sc, bi, (float*)d_out);
}